// round 13
// baseline (speedup 1.0000x reference)
#include <cuda_runtime.h>
#include <cuda_fp16.h>
#include <math.h>
#include <stdint.h>

// Problem constants
#define B_SZ   4
#define T_SZ   16
#define C_SZ   3
#define H_SZ   256
#define W_SZ   256
#define N_PTS  8192
#define PATCH  9
#define EMBED  768
#define PDIM   243
#define KPAD   256
#define M_ROWS 32768

#define NTILES   ((M_ROWS / 128) * (EMBED / 128))   // 1536
#define TILES_X  (EMBED / 128)                      // 6
#define GRID_P   296                                // 2 CTAs/SM * 148

// Scratch (__device__ globals: allocation-free rule)
__device__ __half g_X[(size_t)M_ROWS * KPAD];     // K axis PERMUTED: c*81+dy*9+dx
__device__ __half g_H[(size_t)M_ROWS * EMBED];
__device__ __half g_W1T[(size_t)EMBED * KPAD];    // same K permutation
__device__ __half g_W2T[(size_t)EMBED * EMBED];

__device__ __forceinline__ uint32_t smem_u32(const void* p) {
    uint32_t a;
    asm("{ .reg .u64 t; cvta.to.shared.u64 t, %1; cvt.u32.u64 %0, t; }" : "=r"(a) : "l"(p));
    return a;
}
__device__ __forceinline__ void cp16(uint32_t dst, const void* src) {
    asm volatile("cp.async.cg.shared.global [%0], [%1], 16;" :: "r"(dst), "l"(src));
}
#define CP_COMMIT() asm volatile("cp.async.commit_group;" ::: "memory")
#define CP_WAIT0()  asm volatile("cp.async.wait_group 0;" ::: "memory")
#define CP_WAIT1()  asm volatile("cp.async.wait_group 1;" ::: "memory")

__device__ __forceinline__ void mma_f16(float* c, const uint32_t* a, const uint32_t* b) {
    asm volatile(
        "mma.sync.aligned.m16n8k16.row.col.f32.f16.f16.f32 "
        "{%0,%1,%2,%3}, {%4,%5,%6,%7}, {%8,%9}, {%0,%1,%2,%3};"
        : "+f"(c[0]), "+f"(c[1]), "+f"(c[2]), "+f"(c[3])
        : "r"(a[0]), "r"(a[1]), "r"(a[2]), "r"(a[3]), "r"(b[0]), "r"(b[1]));
}
__device__ __forceinline__ void ldm_x4(uint32_t* r, uint32_t addr) {
    asm volatile("ldmatrix.sync.aligned.m8n8.x4.shared.b16 {%0,%1,%2,%3}, [%4];"
        : "=r"(r[0]), "=r"(r[1]), "=r"(r[2]), "=r"(r[3]) : "r"(addr));
}

// ---------------------------------------------------------------------------
// Gather patches -> g_X fp16, K permuted (c, dy, dx). 4 rows/block, 4 cols/thr.
// ---------------------------------------------------------------------------
__global__ __launch_bounds__(256) void gather_kernel(
    const float* __restrict__ frames,
    const float* __restrict__ coords,
    const int*   __restrict__ t_src)
{
    const int t   = threadIdx.x;
    const int row = blockIdx.x * 4 + (t >> 6);
    const int cc  = t & 63;
    const int b = row >> 13;
    const int n = row & (N_PTS - 1);

    const float cu = coords[(size_t)(b * N_PTS + n) * 2 + 0];
    const float cv = coords[(size_t)(b * N_PTS + n) * 2 + 1];
    const int u = (int)(cu * (float)(W_SZ - 1));
    const int v = (int)(cv * (float)(H_SZ - 1));
    const int tt = t_src[b * N_PTS + n];
    const float* fbase = frames + (((size_t)b * T_SZ + tt) * C_SZ) * H_SZ * W_SZ;

    #pragma unroll
    for (int j = 0; j < 4; j++) {
        int col = cc + j * 64;
        float val = 0.0f;
        if (col < PDIM) {
            int c  = col / 81;
            int r  = col - c * 81;
            int dy = r / 9;
            int dx = r - dy * 9;
            int y = min(max(v + dy - PATCH / 2, 0), H_SZ - 1);
            int x = min(max(u + dx - PATCH / 2, 0), W_SZ - 1);
            val = fbase[((size_t)c * H_SZ + y) * W_SZ + x];
        }
        if (col < KPAD)
            g_X[(size_t)row * KPAD + col] = __float2half_rn(val);
    }
}

// ---------------------------------------------------------------------------
// Tiled weight transpose to fp16; optional K-permutation on the source row.
// ---------------------------------------------------------------------------
template<bool PERM>
__global__ __launch_bounds__(256) void transpose_h(
    const float* __restrict__ in, __half* __restrict__ out,
    int Kin, int Kout, int Nn)
{
    __shared__ float tile[32][33];
    int k0 = blockIdx.y * 32;
    int n0 = blockIdx.x * 32;
    int tx = threadIdx.x & 31;
    int ty = threadIdx.x >> 5;
    #pragma unroll
    for (int i = 0; i < 4; i++) {
        int kp = k0 + ty + i * 8;
        float v = 0.0f;
        if (kp < Kin) {
            int k = kp;
            if (PERM) {
                int c = kp / 81;
                int r = kp - c * 81;
                k = r * 3 + c;
            }
            v = in[(size_t)k * Nn + n0 + tx];
        }
        tile[ty + i * 8][tx] = v;
    }
    __syncthreads();
    #pragma unroll
    for (int i = 0; i < 4; i++) {
        int n = n0 + ty + i * 8;
        out[(size_t)n * Kout + k0 + tx] = __float2half_rn(tile[tx][ty + i * 8]);
    }
}

// ---------------------------------------------------------------------------
// Persistent FP16 m16n8k16 GEMM. Each CTA owns a contiguous balanced run of
// 128x128 tiles; the 3-stage cp.async ring runs continuously ACROSS tiles,
// so prologue latency is paid once per CTA and epilogues overlap next-tile
// loads. Tile order x-fastest (n) -> A tile L2-reuse within a CTA's run.
// smem tiles: 128 rows x 128B, swizzle (granule ^ row&7).
// ---------------------------------------------------------------------------
#define TILE_BYTES 16384
#define NSTAGE     3
#define S_TOTAL    (2 * NSTAGE * TILE_BYTES)   // 98304

__device__ __forceinline__ void load_tile(uint32_t sdst,
                                          const __half* __restrict__ src,
                                          int lds, int t)
{
    #pragma unroll
    for (int i = 0; i < 4; i++) {
        int li = t + 256 * i;
        int row = li >> 3;
        int q   = li & 7;
        cp16(sdst + row * 128 + ((q ^ (row & 7)) << 4),
             src + (size_t)row * lds + q * 8);
    }
}

template<int KT, bool GELU, typename OutT>
__global__ void __launch_bounds__(256, 2) gemm_persist(
    const __half* __restrict__ A,    // [M][lda]
    const __half* __restrict__ BT,   // [768][ldb]
    const float*  __restrict__ bias,
    OutT* __restrict__ C,            // [M][768]
    int lda, int ldb)
{
    extern __shared__ __align__(1024) char smem[];
    const uint32_t sb  = smem_u32(smem);
    const uint32_t sbB = sb + NSTAGE * TILE_BYTES;

    const int t    = threadIdx.x;
    const int w    = t >> 5;
    const int lane = t & 31;
    const int wm   = w & 1;
    const int wn   = w >> 1;

    // Balanced contiguous tile partition: 1536 = GRID_P*5 + 56
    const int bid  = blockIdx.x;
    const int base = NTILES / GRID_P;                 // 5
    const int rem  = NTILES - base * GRID_P;          // 56
    const int t0   = bid * base + min(bid, rem);
    const int cnt  = base + (bid < rem ? 1 : 0);
    const int t1   = t0 + cnt;
    if (cnt <= 0) return;
    const int nchunks = cnt * KT;

    // Fragment addressing (R7 layout)
    const int rA = ((lane >> 3) & 1) * 8 + (lane & 7);
    const int kA = lane >> 4;
    const int rB = ((lane >> 4) & 1) * 8 + (lane & 7);
    const int kB = (lane >> 3) & 1;

    int offA[4], xA[4];
    #pragma unroll
    for (int mt = 0; mt < 4; mt++) {
        int row = wm * 64 + mt * 16 + rA;
        offA[mt] = row * 128;
        xA[mt]   = row & 7;
    }
    int offB[2], xB[2];
    #pragma unroll
    for (int p = 0; p < 2; p++) {
        int row = wn * 32 + p * 16 + rB;
        offB[p] = row * 128;
        xB[p]   = row & 7;
    }

    // Load cursor (tile lt, k-chunk lkt, ring stage ls)
    int lt = t0, lkt = 0, ls = 0;
    auto load_chunk = [&]() {
        const int m = lt / TILES_X;
        const int n = lt - m * TILES_X;
        load_tile(sb  + ls * TILE_BYTES,
                  A  + ((size_t)m * 128) * lda + lkt * 64, lda, t);
        load_tile(sbB + ls * TILE_BYTES,
                  BT + ((size_t)n * 128) * ldb + lkt * 64, ldb, t);
        CP_COMMIT();
        ls = (ls == NSTAGE - 1) ? 0 : ls + 1;
        if (++lkt == KT) { lkt = 0; ++lt; }
    };

    load_chunk();
    if (nchunks > 1) load_chunk();

    int cs = 0;   // compute ring stage
    int q  = 0;   // global chunk counter

    for (int tile = t0; tile < t1; ++tile) {
        float acc[4][4][4];
        #pragma unroll
        for (int i = 0; i < 4; i++)
            #pragma unroll
            for (int j = 0; j < 4; j++)
                #pragma unroll
                for (int r = 0; r < 4; r++) acc[i][j][r] = 0.0f;

        #pragma unroll
        for (int kt = 0; kt < KT; ++kt, ++q) {
            if (q + 2 <= nchunks) { CP_WAIT1(); } else { CP_WAIT0(); }
            __syncthreads();
            if (lt < t1) load_chunk();

            const uint32_t a_base = sb  + cs * TILE_BYTES;
            const uint32_t b_base = sbB + cs * TILE_BYTES;

            #pragma unroll
            for (int ks = 0; ks < 4; ks++) {
                uint32_t af[4][4], bf[4][2];
                #pragma unroll
                for (int mt = 0; mt < 4; mt++)
                    ldm_x4(af[mt], a_base + offA[mt] + (((ks * 2 + kA) ^ xA[mt]) << 4));
                #pragma unroll
                for (int p = 0; p < 2; p++) {
                    uint32_t r[4];
                    ldm_x4(r, b_base + offB[p] + (((ks * 2 + kB) ^ xB[p]) << 4));
                    bf[2 * p][0]     = r[0];
                    bf[2 * p][1]     = r[1];
                    bf[2 * p + 1][0] = r[2];
                    bf[2 * p + 1][1] = r[3];
                }
                #pragma unroll
                for (int mt = 0; mt < 4; mt++)
                    #pragma unroll
                    for (int nt = 0; nt < 4; nt++)
                        mma_f16(acc[mt][nt], af[mt], bf[nt]);
            }
            cs = (cs == NSTAGE - 1) ? 0 : cs + 1;
        }

        // Epilogue (overlaps next tile's in-flight loads)
        const int m   = tile / TILES_X;
        const int n   = tile - m * TILES_X;
        const int bm0 = m * 128;
        const int bn0 = n * 128;
        const int g   = lane >> 2;
        const int tg  = lane & 3;
        #pragma unroll
        for (int nt = 0; nt < 4; nt++) {
            const int col = bn0 + wn * 32 + nt * 8 + 2 * tg;
            const float2 bb = *(const float2*)(bias + col);
            #pragma unroll
            for (int mt = 0; mt < 4; mt++) {
                const int row = bm0 + wm * 64 + mt * 16 + g;
                #pragma unroll
                for (int h = 0; h < 2; h++) {
                    float vx = acc[mt][nt][h * 2 + 0] + bb.x;
                    float vy = acc[mt][nt][h * 2 + 1] + bb.y;
                    if (GELU) {
                        vx = 0.5f * vx * (1.0f + erff(vx * 0.70710678118654752f));
                        vy = 0.5f * vy * (1.0f + erff(vy * 0.70710678118654752f));
                    }
                    OutT* dst = C + (size_t)(row + h * 8) * EMBED + col;
                    if (sizeof(OutT) == 2) {
                        *(__half2*)dst = __floats2half2_rn(vx, vy);
                    } else {
                        *(float2*)dst = make_float2(vx, vy);
                    }
                }
            }
        }
    }
}

// ---------------------------------------------------------------------------
extern "C" void kernel_launch(void* const* d_in, const int* in_sizes, int n_in,
                              void* d_out, int out_size)
{
    const float* frames = (const float*)d_in[0];
    const float* coords = (const float*)d_in[1];
    const int*   t_src  = (const int*)  d_in[2];
    const float* W1     = (const float*)d_in[3];
    const float* b1     = (const float*)d_in[4];
    const float* W2     = (const float*)d_in[5];
    const float* b2     = (const float*)d_in[6];
    float*       out    = (float*)d_out;

    __half *X, *H, *W1T, *W2T;
    cudaGetSymbolAddress((void**)&X,   g_X);
    cudaGetSymbolAddress((void**)&H,   g_H);
    cudaGetSymbolAddress((void**)&W1T, g_W1T);
    cudaGetSymbolAddress((void**)&W2T, g_W2T);

    cudaFuncSetAttribute(gemm_persist<4,  true,  __half>, cudaFuncAttributeMaxDynamicSharedMemorySize, S_TOTAL);
    cudaFuncSetAttribute(gemm_persist<12, false, float>,  cudaFuncAttributeMaxDynamicSharedMemorySize, S_TOTAL);

    gather_kernel<<<M_ROWS / 4, 256>>>(frames, coords, t_src);
    {
        dim3 g1(EMBED / 32, KPAD / 32);
        transpose_h<true><<<g1, 256>>>(W1, W1T, PDIM, KPAD, EMBED);
        dim3 g2(EMBED / 32, EMBED / 32);
        transpose_h<false><<<g2, 256>>>(W2, W2T, EMBED, EMBED, EMBED);
    }

    gemm_persist<4,  true,  __half><<<GRID_P, 256, S_TOTAL>>>(X, W1T, b1, H,   KPAD,  KPAD);
    gemm_persist<12, false, float> <<<GRID_P, 256, S_TOTAL>>>(H, W2T, b2, out, EMBED, EMBED);
}

// round 17
// speedup vs baseline: 1.1314x; 1.1314x over previous
#include <cuda_runtime.h>
#include <cuda_fp16.h>
#include <math.h>
#include <stdint.h>

// Problem constants
#define B_SZ   4
#define T_SZ   16
#define C_SZ   3
#define H_SZ   256
#define W_SZ   256
#define N_PTS  8192
#define PATCH  9
#define EMBED  768
#define PDIM   243
#define KPAD   256
#define M_ROWS 32768

// Scratch (__device__ globals: allocation-free rule)
__device__ __half g_X[(size_t)M_ROWS * KPAD];     // K axis PERMUTED: c*81+dy*9+dx
__device__ __half g_H[(size_t)M_ROWS * EMBED];
__device__ __half g_W1T[(size_t)EMBED * KPAD];    // same K permutation
__device__ __half g_W2T[(size_t)EMBED * EMBED];

__device__ __forceinline__ uint32_t smem_u32(const void* p) {
    uint32_t a;
    asm("{ .reg .u64 t; cvta.to.shared.u64 t, %1; cvt.u32.u64 %0, t; }" : "=r"(a) : "l"(p));
    return a;
}
__device__ __forceinline__ void cp16(uint32_t dst, const void* src) {
    asm volatile("cp.async.cg.shared.global [%0], [%1], 16;" :: "r"(dst), "l"(src));
}
#define CP_COMMIT() asm volatile("cp.async.commit_group;" ::: "memory")
#define CP_WAIT0()  asm volatile("cp.async.wait_group 0;" ::: "memory")
#define CP_WAIT1()  asm volatile("cp.async.wait_group 1;" ::: "memory")

__device__ __forceinline__ void mma_f16(float* c, const uint32_t* a, const uint32_t* b) {
    asm volatile(
        "mma.sync.aligned.m16n8k16.row.col.f32.f16.f16.f32 "
        "{%0,%1,%2,%3}, {%4,%5,%6,%7}, {%8,%9}, {%0,%1,%2,%3};"
        : "+f"(c[0]), "+f"(c[1]), "+f"(c[2]), "+f"(c[3])
        : "r"(a[0]), "r"(a[1]), "r"(a[2]), "r"(a[3]), "r"(b[0]), "r"(b[1]));
}
__device__ __forceinline__ void ldm_x4(uint32_t* r, uint32_t addr) {
    asm volatile("ldmatrix.sync.aligned.m8n8.x4.shared.b16 {%0,%1,%2,%3}, [%4];"
        : "=r"(r[0]), "=r"(r[1]), "=r"(r[2]), "=r"(r[3]) : "r"(addr));
}
__device__ __forceinline__ float ex2f(float x) {
    float y; asm("ex2.approx.f32 %0, %1;" : "=f"(y) : "f"(x)); return y;
}
__device__ __forceinline__ float rcpf(float x) {
    float y; asm("rcp.approx.f32 %0, %1;" : "=f"(y) : "f"(x)); return y;
}
// Fast GELU (tanh/sigmoid form): x * sigmoid(1.59577x + 0.0713548x^3)
// = x * rcp(1 + 2^(x*(-2.3020501 - 0.10294134 x^2)))
__device__ __forceinline__ float fast_gelu(float x) {
    float x2 = x * x;
    float earg = x * fmaf(x2, -0.10294134f, -2.3020501f);
    return x * rcpf(1.0f + ex2f(earg));
}

// ---------------------------------------------------------------------------
// Gather patches -> g_X fp16, K permuted (c, dy, dx). 4 rows/block, 4 cols/thr.
// ---------------------------------------------------------------------------
__global__ __launch_bounds__(256) void gather_kernel(
    const float* __restrict__ frames,
    const float* __restrict__ coords,
    const int*   __restrict__ t_src)
{
    const int t   = threadIdx.x;
    const int row = blockIdx.x * 4 + (t >> 6);
    const int cc  = t & 63;
    const int b = row >> 13;
    const int n = row & (N_PTS - 1);

    const float cu = coords[(size_t)(b * N_PTS + n) * 2 + 0];
    const float cv = coords[(size_t)(b * N_PTS + n) * 2 + 1];
    const int u = (int)(cu * (float)(W_SZ - 1));
    const int v = (int)(cv * (float)(H_SZ - 1));
    const int tt = t_src[b * N_PTS + n];
    const float* fbase = frames + (((size_t)b * T_SZ + tt) * C_SZ) * H_SZ * W_SZ;

    #pragma unroll
    for (int j = 0; j < 4; j++) {
        int col = cc + j * 64;
        float val = 0.0f;
        if (col < PDIM) {
            int c  = col / 81;
            int r  = col - c * 81;
            int dy = r / 9;
            int dx = r - dy * 9;
            int y = min(max(v + dy - PATCH / 2, 0), H_SZ - 1);
            int x = min(max(u + dx - PATCH / 2, 0), W_SZ - 1);
            val = fbase[((size_t)c * H_SZ + y) * W_SZ + x];
        }
        if (col < KPAD)
            g_X[(size_t)row * KPAD + col] = __float2half_rn(val);
    }
}

// ---------------------------------------------------------------------------
// Tiled weight transpose to fp16; optional K-permutation on the source row.
// ---------------------------------------------------------------------------
template<bool PERM>
__global__ __launch_bounds__(256) void transpose_h(
    const float* __restrict__ in, __half* __restrict__ out,
    int Kin, int Kout, int Nn)
{
    __shared__ float tile[32][33];
    int k0 = blockIdx.y * 32;
    int n0 = blockIdx.x * 32;
    int tx = threadIdx.x & 31;
    int ty = threadIdx.x >> 5;
    #pragma unroll
    for (int i = 0; i < 4; i++) {
        int kp = k0 + ty + i * 8;
        float v = 0.0f;
        if (kp < Kin) {
            int k = kp;
            if (PERM) {
                int c = kp / 81;
                int r = kp - c * 81;
                k = r * 3 + c;
            }
            v = in[(size_t)k * Nn + n0 + tx];
        }
        tile[ty + i * 8][tx] = v;
    }
    __syncthreads();
    #pragma unroll
    for (int i = 0; i < 4; i++) {
        int n = n0 + ty + i * 8;
        out[(size_t)n * Kout + k0 + tx] = __float2half_rn(tile[tx][ty + i * 8]);
    }
}

// ---------------------------------------------------------------------------
// FP16 m16n8k16 GEMM, 3-stage cp.async pipeline (R7/R9 best config).
// BM=128 BN=128 BK=64; 256 thr, warps 2M x 4N, warp tile 64x32.
// smem tiles: 128 rows x 128B, swizzle (granule ^ row&7).
// ---------------------------------------------------------------------------
#define TILE_BYTES 16384
#define NSTAGE     3
#define S_TOTAL    (2 * NSTAGE * TILE_BYTES)   // 98304

__device__ __forceinline__ void load_tile(uint32_t sdst,
                                          const __half* __restrict__ src,
                                          int lds, int t)
{
    #pragma unroll
    for (int i = 0; i < 4; i++) {
        int li = t + 256 * i;
        int row = li >> 3;
        int q   = li & 7;
        cp16(sdst + row * 128 + ((q ^ (row & 7)) << 4),
             src + (size_t)row * lds + q * 8);
    }
}

template<int KT, bool GELU, typename OutT>
__global__ void __launch_bounds__(256, 2) gemm_mma(
    const __half* __restrict__ A,    // [M][lda]
    const __half* __restrict__ BT,   // [768][ldb]
    const float*  __restrict__ bias,
    OutT* __restrict__ C,            // [M][768]
    int lda, int ldb)
{
    extern __shared__ __align__(1024) char smem[];
    const uint32_t sb  = smem_u32(smem);
    const uint32_t sbB = sb + NSTAGE * TILE_BYTES;

    const int t    = threadIdx.x;
    const int w    = t >> 5;
    const int lane = t & 31;
    const int wm   = w & 1;
    const int wn   = w >> 1;
    const int bm0  = blockIdx.y * 128;
    const int bn0  = blockIdx.x * 128;

    const int rA = ((lane >> 3) & 1) * 8 + (lane & 7);
    const int kA = lane >> 4;
    const int rB = ((lane >> 4) & 1) * 8 + (lane & 7);
    const int kB = (lane >> 3) & 1;

    int offA[4], xA[4];
    #pragma unroll
    for (int mt = 0; mt < 4; mt++) {
        int row = wm * 64 + mt * 16 + rA;
        offA[mt] = row * 128;
        xA[mt]   = row & 7;
    }
    int offB[2], xB[2];
    #pragma unroll
    for (int p = 0; p < 2; p++) {
        int row = wn * 32 + p * 16 + rB;
        offB[p] = row * 128;
        xB[p]   = row & 7;
    }

    const __half* Ag = A  + (size_t)bm0 * lda;
    const __half* Bg = BT + (size_t)bn0 * ldb;

    float acc[4][4][4];
    #pragma unroll
    for (int i = 0; i < 4; i++)
        #pragma unroll
        for (int j = 0; j < 4; j++)
            #pragma unroll
            for (int r = 0; r < 4; r++) acc[i][j][r] = 0.0f;

    // Prologue: stages 0 and 1 in flight
    load_tile(sb,  Ag, lda, t);
    load_tile(sbB, Bg, ldb, t);
    CP_COMMIT();
    if (KT > 1) {
        load_tile(sb  + TILE_BYTES, Ag + 64, lda, t);
        load_tile(sbB + TILE_BYTES, Bg + 64, ldb, t);
        CP_COMMIT();
    }

    #pragma unroll 3
    for (int kt = 0; kt < KT; kt++) {
        if (kt == KT - 1) { CP_WAIT0(); } else { CP_WAIT1(); }
        __syncthreads();
        if (kt + 2 < KT) {
            const int s = (kt + 2) % NSTAGE;
            load_tile(sb  + s * TILE_BYTES, Ag + (size_t)(kt + 2) * 64, lda, t);
            load_tile(sbB + s * TILE_BYTES, Bg + (size_t)(kt + 2) * 64, ldb, t);
            CP_COMMIT();
        }
        const uint32_t a_base = sb  + (kt % NSTAGE) * TILE_BYTES;
        const uint32_t b_base = sbB + (kt % NSTAGE) * TILE_BYTES;

        #pragma unroll
        for (int ks = 0; ks < 4; ks++) {
            uint32_t af[4][4], bf[4][2];
            #pragma unroll
            for (int mt = 0; mt < 4; mt++)
                ldm_x4(af[mt], a_base + offA[mt] + (((ks * 2 + kA) ^ xA[mt]) << 4));
            #pragma unroll
            for (int p = 0; p < 2; p++) {
                uint32_t r[4];
                ldm_x4(r, b_base + offB[p] + (((ks * 2 + kB) ^ xB[p]) << 4));
                bf[2 * p][0]     = r[0];
                bf[2 * p][1]     = r[1];
                bf[2 * p + 1][0] = r[2];
                bf[2 * p + 1][1] = r[3];
            }
            #pragma unroll
            for (int mt = 0; mt < 4; mt++)
                #pragma unroll
                for (int nt = 0; nt < 4; nt++)
                    mma_f16(acc[mt][nt], af[mt], bf[nt]);
        }
        // no trailing barrier: next iter's top barrier orders buffer reuse
    }

    // Epilogue: bias (+fast GELU), pairwise stores
    const int g  = lane >> 2;
    const int tg = lane & 3;
    #pragma unroll
    for (int nt = 0; nt < 4; nt++) {
        const int col = bn0 + wn * 32 + nt * 8 + 2 * tg;
        const float2 bb = *(const float2*)(bias + col);
        #pragma unroll
        for (int mt = 0; mt < 4; mt++) {
            const int row = bm0 + wm * 64 + mt * 16 + g;
            #pragma unroll
            for (int h = 0; h < 2; h++) {
                float vx = acc[mt][nt][h * 2 + 0] + bb.x;
                float vy = acc[mt][nt][h * 2 + 1] + bb.y;
                if (GELU) {
                    vx = fast_gelu(vx);
                    vy = fast_gelu(vy);
                }
                OutT* dst = C + (size_t)(row + h * 8) * EMBED + col;
                if (sizeof(OutT) == 2) {
                    *(__half2*)dst = __floats2half2_rn(vx, vy);
                } else {
                    *(float2*)dst = make_float2(vx, vy);
                }
            }
        }
    }
}

// ---------------------------------------------------------------------------
extern "C" void kernel_launch(void* const* d_in, const int* in_sizes, int n_in,
                              void* d_out, int out_size)
{
    const float* frames = (const float*)d_in[0];
    const float* coords = (const float*)d_in[1];
    const int*   t_src  = (const int*)  d_in[2];
    const float* W1     = (const float*)d_in[3];
    const float* b1     = (const float*)d_in[4];
    const float* W2     = (const float*)d_in[5];
    const float* b2     = (const float*)d_in[6];
    float*       out    = (float*)d_out;

    __half *X, *H, *W1T, *W2T;
    cudaGetSymbolAddress((void**)&X,   g_X);
    cudaGetSymbolAddress((void**)&H,   g_H);
    cudaGetSymbolAddress((void**)&W1T, g_W1T);
    cudaGetSymbolAddress((void**)&W2T, g_W2T);

    cudaFuncSetAttribute(gemm_mma<4,  true,  __half>, cudaFuncAttributeMaxDynamicSharedMemorySize, S_TOTAL);
    cudaFuncSetAttribute(gemm_mma<12, false, float>,  cudaFuncAttributeMaxDynamicSharedMemorySize, S_TOTAL);

    gather_kernel<<<M_ROWS / 4, 256>>>(frames, coords, t_src);
    {
        dim3 g1(EMBED / 32, KPAD / 32);
        transpose_h<true><<<g1, 256>>>(W1, W1T, PDIM, KPAD, EMBED);
        dim3 g2(EMBED / 32, EMBED / 32);
        transpose_h<false><<<g2, 256>>>(W2, W2T, EMBED, EMBED, EMBED);
    }

    dim3 grid(EMBED / 128, M_ROWS / 128);   // (6, 256), x fastest -> A tiles L2-shared
    gemm_mma<4,  true,  __half><<<grid, 256, S_TOTAL>>>(X, W1T, b1, H,   KPAD,  KPAD);
    gemm_mma<12, false, float> <<<grid, 256, S_TOTAL>>>(H, W2T, b2, out, EMBED, EMBED);
}